// round 11
// baseline (speedup 1.0000x reference)
#include <cuda_runtime.h>
#include <cuda_fp16.h>
#include <math.h>
#include <stdint.h>

#define NN   50000
#define EE   800000
#define ET   (EE + NN)
#define INC  128
#define HC   192
#define OUTC 32

// ---------------- scratch ----------------
__device__ __half g_h[NN * HC];                       // gemm output -> agg input (fp16)
__device__ __half g_hx16[NN * HC];                    // agg output -> gemm input (fp16)
__device__ __half g_x16[NN * INC];                    // x quantized fp16
__device__ float4 g_ew[ET];                           // per-edge exp weights
__device__ __half g_w1thi[HC * INC], g_w1tlo[HC * INC];
__device__ __half g_w2thi[HC * HC],  g_w2tlo[HC * HC];
__device__ __half g_wfthi[OUTC * HC], g_wftlo[OUTC * HC];
__device__ float g_bf[OUTC];
__device__ float g_as[NN * 3];
__device__ float g_ad[NN * 3];
__device__ int   g_deg[NN];
__device__ int   g_ctr[NN];
__device__ int   g_rowptr[NN + 1];
__device__ int   g_srcs[ET];

// ---------------- helpers ----------------
__device__ __forceinline__ float lrelu(float v) { return v > 0.f ? v : 0.2f * v; }
__device__ __forceinline__ float elu_f(float v) { return v > 0.f ? v : expm1f(v); }
__device__ __forceinline__ float wsum(float v) {
    #pragma unroll
    for (int o = 16; o > 0; o >>= 1) v += __shfl_xor_sync(0xffffffffu, v, o);
    return v;
}
__device__ __forceinline__ uint32_t smem_u32(const void* p) {
    uint32_t a;
    asm("{ .reg .u64 t; cvta.to.shared.u64 t, %1; cvt.u32.u64 %0, t; }" : "=r"(a) : "l"(p));
    return a;
}
__device__ __forceinline__ void ldsm4(uint32_t& r0, uint32_t& r1, uint32_t& r2, uint32_t& r3, uint32_t a) {
    asm volatile("ldmatrix.sync.aligned.m8n8.x4.shared.b16 {%0,%1,%2,%3}, [%4];"
                 : "=r"(r0), "=r"(r1), "=r"(r2), "=r"(r3) : "r"(a));
}
__device__ __forceinline__ void mma_f16(float* c, const uint32_t* a, const uint32_t* b) {
    asm volatile(
        "mma.sync.aligned.m16n8k16.row.col.f32.f16.f16.f32 "
        "{%0,%1,%2,%3}, {%4,%5,%6,%7}, {%8,%9}, {%0,%1,%2,%3};"
        : "+f"(c[0]), "+f"(c[1]), "+f"(c[2]), "+f"(c[3])
        : "r"(a[0]), "r"(a[1]), "r"(a[2]), "r"(a[3]), "r"(b[0]), "r"(b[1]));
}
__device__ __forceinline__ void cpasync16(uint32_t dst, const void* src, bool pred) {
    int sz = pred ? 16 : 0;
    asm volatile("cp.async.cg.shared.global [%0], [%1], 16, %2;"
                 :: "r"(dst), "l"(src), "r"(sz) : "memory");
}
__device__ __forceinline__ void cp_commit() { asm volatile("cp.async.commit_group;" ::: "memory"); }
template <int N>
__device__ __forceinline__ void cp_wait() { asm volatile("cp.async.wait_group %0;" :: "n"(N) : "memory"); }

// ---------------- CSR build (4 independent edges/thread -> 4x atomic MLP) ----------------
#define T4 ((ET + 3) / 4)

__global__ void zero_kernel() {
    int i = blockIdx.x * blockDim.x + threadIdx.x;
    if (i < NN) { g_deg[i] = 0; g_ctr[i] = 0; }
}
__global__ void count_kernel(const int* __restrict__ dst) {
    int tid = blockIdx.x * blockDim.x + threadIdx.x;
    if (tid >= T4) return;                         // mask tail: segments tile [0,ET) exactly
    #pragma unroll
    for (int j = 0; j < 4; j++) {
        int i = tid + j * T4;
        if (i < ET) {
            int d = (i < EE) ? dst[i] : (i - EE);
            atomicAdd(&g_deg[d], 1);
        }
    }
}
__global__ void scan_kernel() {
    __shared__ int part[1024];
    const int per = (NN + 1023) / 1024;
    int t = threadIdx.x;
    int start = t * per, end = min(start + per, NN);
    int s = 0;
    for (int i = start; i < end; i++) s += g_deg[i];
    part[t] = s;
    __syncthreads();
    for (int off = 1; off < 1024; off <<= 1) {
        int v = (t >= off) ? part[t - off] : 0;
        __syncthreads();
        part[t] += v;
        __syncthreads();
    }
    int run = part[t] - s;
    for (int i = start; i < end; i++) { g_rowptr[i] = run; run += g_deg[i]; }
    if (t == 1023) g_rowptr[NN] = part[1023];
}
__global__ void bucket_kernel(const int* __restrict__ src, const int* __restrict__ dst) {
    int tid = blockIdx.x * blockDim.x + threadIdx.x;
    if (tid >= T4) return;                         // mask tail: no duplicate segments
    #pragma unroll
    for (int j = 0; j < 4; j++) {
        int i = tid + j * T4;
        if (i < ET) {
            int s, d;
            if (i < EE) { s = src[i]; d = dst[i]; } else { s = i - EE; d = s; }
            int pos = atomicAdd(&g_ctr[d], 1);
            g_srcs[g_rowptr[d] + pos] = s;
        }
    }
}

// ---------------- operand prep ----------------
// merged: x -> fp16 table  +  W1 -> transposed fp16 hi/lo
__global__ void prep_kernel(const float* __restrict__ x, __half* __restrict__ x16,
                            const float* __restrict__ W1, __half* __restrict__ thi,
                            __half* __restrict__ tlo) {
    const int n4 = NN * INC / 4;
    int i = blockIdx.x * blockDim.x + threadIdx.x;
    if (i < n4) {
        float4 v = ((const float4*)x)[i];
        __half2 a = __floats2half2_rn(v.x, v.y);
        __half2 b = __floats2half2_rn(v.z, v.w);
        ((uint2*)x16)[i] = make_uint2(*(uint32_t*)&a, *(uint32_t*)&b);
    } else {
        int j = i - n4;
        if (j < INC * HC) {
            int k = j / HC, c = j - k * HC;
            float v = W1[j];
            __half h = __float2half_rn(v);
            thi[c * INC + k] = h;
            tlo[c * INC + k] = __float2half_rn(v - __half2float(h));
        }
    }
}
__global__ void wsplit_kernel(const float* __restrict__ W, __half* __restrict__ thi,
                              __half* __restrict__ tlo, int K, int Nc) {
    int i = blockIdx.x * blockDim.x + threadIdx.x;
    if (i >= K * Nc) return;
    int k = i / Nc, c = i - k * Nc;
    float v = W[i];
    __half h = __float2half_rn(v);
    thi[c * K + k] = h;
    tlo[c * K + k] = __float2half_rn(v - __half2float(h));
}
__global__ void fuse_mlp_kernel(const float* __restrict__ Wf1, const float* __restrict__ bf1,
                                const float* __restrict__ Wf2, const float* __restrict__ bf2) {
    int i = blockIdx.x * blockDim.x + threadIdx.x;
    if (i < HC * OUTC) {
        int r = i >> 5, c = i & 31;
        float s = 0.f;
        #pragma unroll 8
        for (int j = 0; j < 64; j++) s += Wf1[r * 64 + j] * Wf2[j * OUTC + c];
        __half h = __float2half_rn(s);
        g_wfthi[c * HC + r] = h;
        g_wftlo[c * HC + r] = __float2half_rn(s - __half2float(h));
    } else if (i < HC * OUTC + OUTC) {
        int c = i - HC * OUTC;
        float s = bf2[c];
        for (int j = 0; j < 64; j++) s += bf1[j] * Wf2[j * OUTC + c];
        g_bf[c] = s;
    }
}

// ---------------- fp16 A x fp16-split B tensor-core GEMM, double-buffered ----------------
#define BM 128
#define BN 64
#define BK 32
#define RS 40
#define SA_OFF 0
#define SB_HI  5120
#define SB_LO  7680
#define STAGE  10240
#define SMEMB (2 * STAGE * 2)   // 40960 bytes

template <bool FUSE, bool OUT16>
__global__ void __launch_bounds__(256, 3) gemm_f16(const __half* __restrict__ A,
                                                   const __half* __restrict__ Bthi,
                                                   const __half* __restrict__ Btlo,
                                                   const float* __restrict__ bias,
                                                   void* __restrict__ Cv,
                                                   const float* __restrict__ asrc,
                                                   const float* __restrict__ adst,
                                                   int M, int K, int Nc) {
    extern __shared__ __half smem[];
    uint32_t sbase = smem_u32(smem);

    int tid = threadIdx.x;
    int lane = tid & 31, warp = tid >> 5;
    int wm = warp & 3, wn = warp >> 2;
    int row0 = blockIdx.y * BM, col0 = blockIdx.x * BN;

    int aRow = ((lane & 8) ? 8 : 0) + (lane & 7);
    int aChk = (lane & 16) ? 1 : 0;

    float acc[2][4][4];
    #pragma unroll
    for (int i = 0; i < 2; i++)
        #pragma unroll
        for (int j = 0; j < 4; j++)
            #pragma unroll
            for (int k = 0; k < 4; k++) acc[i][j][k] = 0.f;

    const int ntiles = K / BK;

    auto load_stage = [&](int t, int st) {
        uint32_t sb = sbase + (uint32_t)(st * STAGE * 2);
        int kt = t * BK;
        #pragma unroll
        for (int j = 0; j < 2; j++) {
            int idx = tid + j * 256;
            int r = idx >> 2, ch = idx & 3;
            int gr = row0 + r;
            bool p = gr < M;
            size_t go = (size_t)gr * K + kt + ch * 8;
            uint32_t dof = (uint32_t)((r * RS + ch * 8) * 2);
            cpasync16(sb + SA_OFF * 2 + dof, A + go, p);
        }
        {
            int r = tid >> 2, ch = tid & 3;
            int gc = col0 + r;
            bool p = gc < Nc;
            size_t go = (size_t)gc * K + kt + ch * 8;
            uint32_t dof = (uint32_t)((r * RS + ch * 8) * 2);
            cpasync16(sb + SB_HI * 2 + dof, Bthi + go, p);
            cpasync16(sb + SB_LO * 2 + dof, Btlo + go, p);
        }
        cp_commit();
    };

    load_stage(0, 0);

    for (int t = 0; t < ntiles; t++) {
        if (t + 1 < ntiles) { load_stage(t + 1, (t + 1) & 1); cp_wait<1>(); }
        else cp_wait<0>();
        __syncthreads();

        uint32_t sb = sbase + (uint32_t)((t & 1) * STAGE * 2);
        uint32_t uA = sb + SA_OFF * 2;
        uint32_t uBhi = sb + SB_HI * 2, uBlo = sb + SB_LO * 2;

        #pragma unroll
        for (int s = 0; s < 2; s++) {
            int kc = 2 * s;
            uint32_t a0[4], a1[4];
            {
                uint32_t base = (uint32_t)(((wm * 32 + aRow) * RS + (kc + aChk) * 8) * 2);
                ldsm4(a0[0], a0[1], a0[2], a0[3], uA + base);
                uint32_t base1 = base + (uint32_t)(16 * RS * 2);
                ldsm4(a1[0], a1[1], a1[2], a1[3], uA + base1);
            }
            uint32_t bh_a[4], bh_b[4], bl_a[4], bl_b[4];
            {
                uint32_t base = (uint32_t)(((wn * 32 + lane) * RS + kc * 8) * 2);
                ldsm4(bh_a[0], bh_a[1], bh_a[2], bh_a[3], uBhi + base);
                ldsm4(bl_a[0], bl_a[1], bl_a[2], bl_a[3], uBlo + base);
                uint32_t base1 = base + 16;
                ldsm4(bh_b[0], bh_b[1], bh_b[2], bh_b[3], uBhi + base1);
                ldsm4(bl_b[0], bl_b[1], bl_b[2], bl_b[3], uBlo + base1);
            }
            #pragma unroll
            for (int ni = 0; ni < 4; ni++) {
                uint32_t bh[2] = {bh_a[ni], bh_b[ni]};
                uint32_t bl[2] = {bl_a[ni], bl_b[ni]};
                mma_f16(acc[0][ni], a0, bh);
                mma_f16(acc[0][ni], a0, bl);
                mma_f16(acc[1][ni], a1, bh);
                mma_f16(acc[1][ni], a1, bl);
            }
        }
        __syncthreads();
    }

    // ---- epilogue: C store ----
    int lq = lane >> 2, lr = lane & 3;
    #pragma unroll
    for (int mi = 0; mi < 2; mi++) {
        int r0 = row0 + wm * 32 + mi * 16 + lq;
        #pragma unroll
        for (int ni = 0; ni < 4; ni++) {
            int c = col0 + wn * 32 + ni * 8 + lr * 2;
            if (c < Nc) {
                if (OUT16) {
                    __half* C = (__half*)Cv;
                    if (r0 < M)
                        *(__half2*)(C + (size_t)r0 * Nc + c) =
                            __floats2half2_rn(acc[mi][ni][0], acc[mi][ni][1]);
                    if (r0 + 8 < M)
                        *(__half2*)(C + (size_t)(r0 + 8) * Nc + c) =
                            __floats2half2_rn(acc[mi][ni][2], acc[mi][ni][3]);
                } else {
                    float* C = (float*)Cv;
                    float b0 = bias ? bias[c] : 0.f;
                    float b1 = bias ? bias[c + 1] : 0.f;
                    if (r0 < M)
                        *(float2*)(C + (size_t)r0 * Nc + c) =
                            make_float2(acc[mi][ni][0] + b0, acc[mi][ni][1] + b1);
                    if (r0 + 8 < M)
                        *(float2*)(C + (size_t)(r0 + 8) * Nc + c) =
                            make_float2(acc[mi][ni][2] + b0, acc[mi][ni][3] + b1);
                }
            }
        }
    }

    // ---- fused alpha projections (head = col tile), atomic-free ----
    if (FUSE) {
        float* sred = (float*)smem;
        int head = col0 >> 6;
        #pragma unroll
        for (int mi = 0; mi < 2; mi++) {
            float s0 = 0.f, s1 = 0.f, d0 = 0.f, d1 = 0.f;
            #pragma unroll
            for (int ni = 0; ni < 4; ni++) {
                int c = col0 + wn * 32 + ni * 8 + lr * 2;
                float ws0 = asrc[c], ws1 = asrc[c + 1];
                float wd0 = adst[c], wd1 = adst[c + 1];
                s0 += acc[mi][ni][0] * ws0 + acc[mi][ni][1] * ws1;
                s1 += acc[mi][ni][2] * ws0 + acc[mi][ni][3] * ws1;
                d0 += acc[mi][ni][0] * wd0 + acc[mi][ni][1] * wd1;
                d1 += acc[mi][ni][2] * wd0 + acc[mi][ni][3] * wd1;
            }
            #pragma unroll
            for (int o = 1; o <= 2; o <<= 1) {
                s0 += __shfl_xor_sync(0xffffffffu, s0, o);
                s1 += __shfl_xor_sync(0xffffffffu, s1, o);
                d0 += __shfl_xor_sync(0xffffffffu, d0, o);
                d1 += __shfl_xor_sync(0xffffffffu, d1, o);
            }
            if (lr == 0) {
                int rl0 = wm * 32 + mi * 16 + lq;
                sred[rl0 * 2 + wn] = s0;
                sred[(rl0 + 8) * 2 + wn] = s1;
                sred[256 + rl0 * 2 + wn] = d0;
                sred[256 + (rl0 + 8) * 2 + wn] = d1;
            }
        }
        __syncthreads();
        if (tid < 128) {
            int gr = row0 + tid;
            if (gr < M) {
                g_as[gr * 3 + head] = sred[tid * 2] + sred[tid * 2 + 1];
                g_ad[gr * 3 + head] = sred[256 + tid * 2] + sred[256 + tid * 2 + 1];
            }
        }
    }
}

// ---------------- GAT aggregation: warp/node, exp once per edge, fp16 I/O ----------------
__global__ void agg_kernel(const __half* __restrict__ h, const float* __restrict__ bias,
                           __half* __restrict__ o16) {
    int gw = (blockIdx.x * blockDim.x + threadIdx.x) >> 5;
    int lane = threadIdx.x & 31;
    if (gw >= NN) return;
    int beg = g_rowptr[gw], end = g_rowptr[gw + 1];
    float ad0 = g_ad[gw * 3 + 0], ad1 = g_ad[gw * 3 + 1], ad2 = g_ad[gw * 3 + 2];

    float d0 = 0.f, d1 = 0.f, d2 = 0.f;
    for (int i = beg + lane; i < end; i += 32) {
        int s = g_srcs[i];
        float e0 = __expf(lrelu(g_as[s * 3 + 0] + ad0));
        float e1 = __expf(lrelu(g_as[s * 3 + 1] + ad1));
        float e2 = __expf(lrelu(g_as[s * 3 + 2] + ad2));
        g_ew[i] = make_float4(e0, e1, e2, 0.f);
        d0 += e0; d1 += e1; d2 += e2;
    }
    d0 = wsum(d0); d1 = wsum(d1); d2 = wsum(d2);
    float i0 = 1.f / (d0 + 1e-16f), i1 = 1.f / (d1 + 1e-16f), i2 = 1.f / (d2 + 1e-16f);

    float2 a0 = make_float2(0.f, 0.f), a1 = a0, a2 = a0;
    #pragma unroll 4
    for (int i = beg; i < end; i++) {
        int s = g_srcs[i];
        float4 w = g_ew[i];
        const __half2* hs = (const __half2*)(h + (size_t)s * HC);
        float2 f0 = __half22float2(hs[lane]);
        float2 f1 = __half22float2(hs[32 + lane]);
        float2 f2 = __half22float2(hs[64 + lane]);
        a0.x += f0.x * w.x; a0.y += f0.y * w.x;
        a1.x += f1.x * w.y; a1.y += f1.y * w.y;
        a2.x += f2.x * w.z; a2.y += f2.y * w.z;
    }
    a0.x *= i0; a0.y *= i0;
    a1.x *= i1; a1.y *= i1;
    a2.x *= i2; a2.y *= i2;

    float2 av[3] = {a0, a1, a2};
    #pragma unroll
    for (int q = 0; q < 3; q++) {
        int c = q * 64 + 2 * lane;
        float v0 = elu_f(av[q].x + bias[c]);
        float v1 = elu_f(av[q].y + bias[c + 1]);
        *(__half2*)(o16 + (size_t)gw * HC + c) = __floats2half2_rn(v0, v1);
    }
}

// ---------------- side-stream resources ----------------
static cudaStream_t g_s2;
static cudaEvent_t  g_evFork, g_evJoin;
static struct SideInit {
    SideInit() {
        cudaStreamCreateWithFlags(&g_s2, cudaStreamNonBlocking);
        cudaEventCreateWithFlags(&g_evFork, cudaEventDisableTiming);
        cudaEventCreateWithFlags(&g_evJoin, cudaEventDisableTiming);
    }
} g_sideInit;

// ---------------- launch ----------------
extern "C" void kernel_launch(void* const* d_in, const int* in_sizes, int n_in,
                              void* d_out, int out_size) {
    const float* x     = (const float*)d_in[0];
    const int*   ei    = (const int*)  d_in[1];
    const float* W1    = (const float*)d_in[2];
    const float* asrc1 = (const float*)d_in[3];
    const float* adst1 = (const float*)d_in[4];
    const float* b1    = (const float*)d_in[5];
    const float* W2    = (const float*)d_in[6];
    const float* asrc2 = (const float*)d_in[7];
    const float* adst2 = (const float*)d_in[8];
    const float* b2    = (const float*)d_in[9];
    const float* Wf1   = (const float*)d_in[10];
    const float* bf1   = (const float*)d_in[11];
    const float* Wf2   = (const float*)d_in[12];
    const float* bf2   = (const float*)d_in[13];
    float* out = (float*)d_out;

    float *bf;
    __half *h, *hx16, *x16, *w1thi, *w1tlo, *w2thi, *w2tlo, *wfthi, *wftlo;
    cudaGetSymbolAddress((void**)&h,     g_h);
    cudaGetSymbolAddress((void**)&hx16,  g_hx16);
    cudaGetSymbolAddress((void**)&x16,   g_x16);
    cudaGetSymbolAddress((void**)&bf,    g_bf);
    cudaGetSymbolAddress((void**)&w1thi, g_w1thi);
    cudaGetSymbolAddress((void**)&w1tlo, g_w1tlo);
    cudaGetSymbolAddress((void**)&w2thi, g_w2thi);
    cudaGetSymbolAddress((void**)&w2tlo, g_w2tlo);
    cudaGetSymbolAddress((void**)&wfthi, g_wfthi);
    cudaGetSymbolAddress((void**)&wftlo, g_wftlo);

    const int* srcp = ei;
    const int* dstp = ei + EE;

    cudaFuncSetAttribute(gemm_f16<true, true>,   cudaFuncAttributeMaxDynamicSharedMemorySize, SMEMB);
    cudaFuncSetAttribute(gemm_f16<false, false>, cudaFuncAttributeMaxDynamicSharedMemorySize, SMEMB);

    int warpBlocks = (NN * 32 + 255) / 256;
    int gy = (NN + BM - 1) / BM;
    int csrBlocks = (T4 + 255) / 256;

    // ---- fork: CSR build + W2/MLP weight prep on side stream ----
    cudaEventRecord(g_evFork, 0);
    cudaStreamWaitEvent(g_s2, g_evFork, 0);
    zero_kernel<<<(NN + 255) / 256, 256, 0, g_s2>>>();
    count_kernel<<<csrBlocks, 256, 0, g_s2>>>(dstp);
    scan_kernel<<<1, 1024, 0, g_s2>>>();
    bucket_kernel<<<csrBlocks, 256, 0, g_s2>>>(srcp, dstp);
    wsplit_kernel<<<(HC * HC + 255) / 256, 256, 0, g_s2>>>(W2, w2thi, w2tlo, HC, HC);
    fuse_mlp_kernel<<<(HC * OUTC + OUTC + 255) / 256, 256, 0, g_s2>>>(Wf1, bf1, Wf2, bf2);
    cudaEventRecord(g_evJoin, g_s2);

    // ---- main stream: merged prep + layer-1 GEMM (+fused alpha) ----
    prep_kernel<<<(NN * INC / 4 + INC * HC + 255) / 256, 256>>>(x, x16, W1, w1thi, w1tlo);
    gemm_f16<true, true><<<dim3(HC / BN, gy), 256, SMEMB>>>(x16, w1thi, w1tlo, nullptr, h,
                                                            asrc1, adst1, NN, INC, HC);

    // ---- join: agg needs CSR; gemm2 needs W2 tables ----
    cudaStreamWaitEvent(0, g_evJoin, 0);
    agg_kernel<<<warpBlocks, 256>>>(h, b1, hx16);

    // layer 2
    gemm_f16<true, true><<<dim3(HC / BN, gy), 256, SMEMB>>>(hx16, w2thi, w2tlo, nullptr, h,
                                                            asrc2, adst2, NN, HC, HC);
    agg_kernel<<<warpBlocks, 256>>>(h, b2, hx16);

    // fused MLP head
    gemm_f16<false, false><<<dim3(1, gy), 256, SMEMB>>>(hx16, wfthi, wftlo, bf, out,
                                                        nullptr, nullptr, NN, HC, OUTC);
}

// round 12
// speedup vs baseline: 1.0246x; 1.0246x over previous
#include <cuda_runtime.h>
#include <cuda_fp16.h>
#include <math.h>
#include <stdint.h>

#define NN   50000
#define EE   800000
#define ET   (EE + NN)
#define INC  128
#define HC   192
#define OUTC 32

// ---------------- scratch ----------------
__device__ __half g_h[NN * HC];                       // gemm output -> agg input (fp16)
__device__ __half g_hx16[NN * HC];                    // agg output -> gemm input (fp16)
__device__ __half g_x16[NN * INC];                    // x quantized fp16
__device__ __half g_w1thi[HC * INC], g_w1tlo[HC * INC];
__device__ __half g_w2thi[HC * HC],  g_w2tlo[HC * HC];
__device__ __half g_wfthi[OUTC * HC], g_wftlo[OUTC * HC];
__device__ float g_bf[OUTC];
__device__ float g_as[NN * 3];
__device__ float g_ad[NN * 3];
__device__ int   g_deg[NN];
__device__ int   g_ctr[NN];
__device__ int   g_rowptr[NN + 1];
__device__ int   g_srcs[ET];

// ---------------- helpers ----------------
__device__ __forceinline__ float lrelu(float v) { return v > 0.f ? v : 0.2f * v; }
__device__ __forceinline__ float elu_f(float v) { return v > 0.f ? v : expm1f(v); }
__device__ __forceinline__ float wsum(float v) {
    #pragma unroll
    for (int o = 16; o > 0; o >>= 1) v += __shfl_xor_sync(0xffffffffu, v, o);
    return v;
}
__device__ __forceinline__ uint32_t smem_u32(const void* p) {
    uint32_t a;
    asm("{ .reg .u64 t; cvta.to.shared.u64 t, %1; cvt.u32.u64 %0, t; }" : "=r"(a) : "l"(p));
    return a;
}
__device__ __forceinline__ void ldsm4(uint32_t& r0, uint32_t& r1, uint32_t& r2, uint32_t& r3, uint32_t a) {
    asm volatile("ldmatrix.sync.aligned.m8n8.x4.shared.b16 {%0,%1,%2,%3}, [%4];"
                 : "=r"(r0), "=r"(r1), "=r"(r2), "=r"(r3) : "r"(a));
}
__device__ __forceinline__ void mma_f16(float* c, const uint32_t* a, const uint32_t* b) {
    asm volatile(
        "mma.sync.aligned.m16n8k16.row.col.f32.f16.f16.f32 "
        "{%0,%1,%2,%3}, {%4,%5,%6,%7}, {%8,%9}, {%0,%1,%2,%3};"
        : "+f"(c[0]), "+f"(c[1]), "+f"(c[2]), "+f"(c[3])
        : "r"(a[0]), "r"(a[1]), "r"(a[2]), "r"(a[3]), "r"(b[0]), "r"(b[1]));
}
__device__ __forceinline__ void cpasync16(uint32_t dst, const void* src, bool pred) {
    int sz = pred ? 16 : 0;
    asm volatile("cp.async.cg.shared.global [%0], [%1], 16, %2;"
                 :: "r"(dst), "l"(src), "r"(sz) : "memory");
}
__device__ __forceinline__ void cp_commit() { asm volatile("cp.async.commit_group;" ::: "memory"); }
template <int N>
__device__ __forceinline__ void cp_wait() { asm volatile("cp.async.wait_group %0;" :: "n"(N) : "memory"); }

// ---------------- CSR build (1 edge/thread; L2-atomic-throughput bound) ----------------
__global__ void zero_kernel() {
    int i = blockIdx.x * blockDim.x + threadIdx.x;
    if (i < NN) { g_deg[i] = 0; g_ctr[i] = 0; }
}
__global__ void count_kernel(const int* __restrict__ dst) {
    int i = blockIdx.x * blockDim.x + threadIdx.x;
    if (i >= ET) return;
    int d = (i < EE) ? dst[i] : (i - EE);
    atomicAdd(&g_deg[d], 1);
}
__global__ void scan_kernel() {
    __shared__ int part[1024];
    const int per = (NN + 1023) / 1024;
    int t = threadIdx.x;
    int start = t * per, end = min(start + per, NN);
    int s = 0;
    for (int i = start; i < end; i++) s += g_deg[i];
    part[t] = s;
    __syncthreads();
    for (int off = 1; off < 1024; off <<= 1) {
        int v = (t >= off) ? part[t - off] : 0;
        __syncthreads();
        part[t] += v;
        __syncthreads();
    }
    int run = part[t] - s;
    for (int i = start; i < end; i++) { g_rowptr[i] = run; run += g_deg[i]; }
    if (t == 1023) g_rowptr[NN] = part[1023];
}
__global__ void bucket_kernel(const int* __restrict__ src, const int* __restrict__ dst) {
    int i = blockIdx.x * blockDim.x + threadIdx.x;
    if (i >= ET) return;
    int s, d;
    if (i < EE) { s = src[i]; d = dst[i]; } else { s = i - EE; d = s; }
    int pos = atomicAdd(&g_ctr[d], 1);
    g_srcs[g_rowptr[d] + pos] = s;
}

// ---------------- operand prep ----------------
__global__ void prep_kernel(const float* __restrict__ x, __half* __restrict__ x16,
                            const float* __restrict__ W1, __half* __restrict__ thi,
                            __half* __restrict__ tlo) {
    const int n4 = NN * INC / 4;
    int i = blockIdx.x * blockDim.x + threadIdx.x;
    if (i < n4) {
        float4 v = ((const float4*)x)[i];
        __half2 a = __floats2half2_rn(v.x, v.y);
        __half2 b = __floats2half2_rn(v.z, v.w);
        ((uint2*)x16)[i] = make_uint2(*(uint32_t*)&a, *(uint32_t*)&b);
    } else {
        int j = i - n4;
        if (j < INC * HC) {
            int k = j / HC, c = j - k * HC;
            float v = W1[j];
            __half h = __float2half_rn(v);
            thi[c * INC + k] = h;
            tlo[c * INC + k] = __float2half_rn(v - __half2float(h));
        }
    }
}
__global__ void wsplit_kernel(const float* __restrict__ W, __half* __restrict__ thi,
                              __half* __restrict__ tlo, int K, int Nc) {
    int i = blockIdx.x * blockDim.x + threadIdx.x;
    if (i >= K * Nc) return;
    int k = i / Nc, c = i - k * Nc;
    float v = W[i];
    __half h = __float2half_rn(v);
    thi[c * K + k] = h;
    tlo[c * K + k] = __float2half_rn(v - __half2float(h));
}
__global__ void fuse_mlp_kernel(const float* __restrict__ Wf1, const float* __restrict__ bf1,
                                const float* __restrict__ Wf2, const float* __restrict__ bf2) {
    int i = blockIdx.x * blockDim.x + threadIdx.x;
    if (i < HC * OUTC) {
        int r = i >> 5, c = i & 31;
        float s = 0.f;
        #pragma unroll 8
        for (int j = 0; j < 64; j++) s += Wf1[r * 64 + j] * Wf2[j * OUTC + c];
        __half h = __float2half_rn(s);
        g_wfthi[c * HC + r] = h;
        g_wftlo[c * HC + r] = __float2half_rn(s - __half2float(h));
    } else if (i < HC * OUTC + OUTC) {
        int c = i - HC * OUTC;
        float s = bf2[c];
        for (int j = 0; j < 64; j++) s += bf1[j] * Wf2[j * OUTC + c];
        g_bf[c] = s;
    }
}

// ---------------- fp16 A x fp16-split B tensor-core GEMM, double-buffered ----------------
#define BM 128
#define BN 64
#define BK 32
#define RS 40
#define SA_OFF 0
#define SB_HI  5120
#define SB_LO  7680
#define STAGE  10240
#define SMEMB (2 * STAGE * 2)   // 40960 bytes

template <bool FUSE, bool OUT16>
__global__ void __launch_bounds__(256, 3) gemm_f16(const __half* __restrict__ A,
                                                   const __half* __restrict__ Bthi,
                                                   const __half* __restrict__ Btlo,
                                                   const float* __restrict__ bias,
                                                   void* __restrict__ Cv,
                                                   const float* __restrict__ asrc,
                                                   const float* __restrict__ adst,
                                                   int M, int K, int Nc) {
    extern __shared__ __half smem[];
    uint32_t sbase = smem_u32(smem);

    int tid = threadIdx.x;
    int lane = tid & 31, warp = tid >> 5;
    int wm = warp & 3, wn = warp >> 2;
    int row0 = blockIdx.y * BM, col0 = blockIdx.x * BN;

    int aRow = ((lane & 8) ? 8 : 0) + (lane & 7);
    int aChk = (lane & 16) ? 1 : 0;

    float acc[2][4][4];
    #pragma unroll
    for (int i = 0; i < 2; i++)
        #pragma unroll
        for (int j = 0; j < 4; j++)
            #pragma unroll
            for (int k = 0; k < 4; k++) acc[i][j][k] = 0.f;

    const int ntiles = K / BK;

    auto load_stage = [&](int t, int st) {
        uint32_t sb = sbase + (uint32_t)(st * STAGE * 2);
        int kt = t * BK;
        #pragma unroll
        for (int j = 0; j < 2; j++) {
            int idx = tid + j * 256;
            int r = idx >> 2, ch = idx & 3;
            int gr = row0 + r;
            bool p = gr < M;
            size_t go = (size_t)gr * K + kt + ch * 8;
            uint32_t dof = (uint32_t)((r * RS + ch * 8) * 2);
            cpasync16(sb + SA_OFF * 2 + dof, A + go, p);
        }
        {
            int r = tid >> 2, ch = tid & 3;
            int gc = col0 + r;
            bool p = gc < Nc;
            size_t go = (size_t)gc * K + kt + ch * 8;
            uint32_t dof = (uint32_t)((r * RS + ch * 8) * 2);
            cpasync16(sb + SB_HI * 2 + dof, Bthi + go, p);
            cpasync16(sb + SB_LO * 2 + dof, Btlo + go, p);
        }
        cp_commit();
    };

    load_stage(0, 0);

    for (int t = 0; t < ntiles; t++) {
        if (t + 1 < ntiles) { load_stage(t + 1, (t + 1) & 1); cp_wait<1>(); }
        else cp_wait<0>();
        __syncthreads();

        uint32_t sb = sbase + (uint32_t)((t & 1) * STAGE * 2);
        uint32_t uA = sb + SA_OFF * 2;
        uint32_t uBhi = sb + SB_HI * 2, uBlo = sb + SB_LO * 2;

        #pragma unroll
        for (int s = 0; s < 2; s++) {
            int kc = 2 * s;
            uint32_t a0[4], a1[4];
            {
                uint32_t base = (uint32_t)(((wm * 32 + aRow) * RS + (kc + aChk) * 8) * 2);
                ldsm4(a0[0], a0[1], a0[2], a0[3], uA + base);
                uint32_t base1 = base + (uint32_t)(16 * RS * 2);
                ldsm4(a1[0], a1[1], a1[2], a1[3], uA + base1);
            }
            uint32_t bh_a[4], bh_b[4], bl_a[4], bl_b[4];
            {
                uint32_t base = (uint32_t)(((wn * 32 + lane) * RS + kc * 8) * 2);
                ldsm4(bh_a[0], bh_a[1], bh_a[2], bh_a[3], uBhi + base);
                ldsm4(bl_a[0], bl_a[1], bl_a[2], bl_a[3], uBlo + base);
                uint32_t base1 = base + 16;
                ldsm4(bh_b[0], bh_b[1], bh_b[2], bh_b[3], uBhi + base1);
                ldsm4(bl_b[0], bl_b[1], bl_b[2], bl_b[3], uBlo + base1);
            }
            #pragma unroll
            for (int ni = 0; ni < 4; ni++) {
                uint32_t bh[2] = {bh_a[ni], bh_b[ni]};
                uint32_t bl[2] = {bl_a[ni], bl_b[ni]};
                mma_f16(acc[0][ni], a0, bh);
                mma_f16(acc[0][ni], a0, bl);
                mma_f16(acc[1][ni], a1, bh);
                mma_f16(acc[1][ni], a1, bl);
            }
        }
        __syncthreads();
    }

    // ---- epilogue: C store ----
    int lq = lane >> 2, lr = lane & 3;
    #pragma unroll
    for (int mi = 0; mi < 2; mi++) {
        int r0 = row0 + wm * 32 + mi * 16 + lq;
        #pragma unroll
        for (int ni = 0; ni < 4; ni++) {
            int c = col0 + wn * 32 + ni * 8 + lr * 2;
            if (c < Nc) {
                if (OUT16) {
                    __half* C = (__half*)Cv;
                    if (r0 < M)
                        *(__half2*)(C + (size_t)r0 * Nc + c) =
                            __floats2half2_rn(acc[mi][ni][0], acc[mi][ni][1]);
                    if (r0 + 8 < M)
                        *(__half2*)(C + (size_t)(r0 + 8) * Nc + c) =
                            __floats2half2_rn(acc[mi][ni][2], acc[mi][ni][3]);
                } else {
                    float* C = (float*)Cv;
                    float b0 = bias ? bias[c] : 0.f;
                    float b1 = bias ? bias[c + 1] : 0.f;
                    if (r0 < M)
                        *(float2*)(C + (size_t)r0 * Nc + c) =
                            make_float2(acc[mi][ni][0] + b0, acc[mi][ni][1] + b1);
                    if (r0 + 8 < M)
                        *(float2*)(C + (size_t)(r0 + 8) * Nc + c) =
                            make_float2(acc[mi][ni][2] + b0, acc[mi][ni][3] + b1);
                }
            }
        }
    }

    // ---- fused alpha projections (head = col tile), atomic-free ----
    if (FUSE) {
        float* sred = (float*)smem;
        int head = col0 >> 6;
        #pragma unroll
        for (int mi = 0; mi < 2; mi++) {
            float s0 = 0.f, s1 = 0.f, d0 = 0.f, d1 = 0.f;
            #pragma unroll
            for (int ni = 0; ni < 4; ni++) {
                int c = col0 + wn * 32 + ni * 8 + lr * 2;
                float ws0 = asrc[c], ws1 = asrc[c + 1];
                float wd0 = adst[c], wd1 = adst[c + 1];
                s0 += acc[mi][ni][0] * ws0 + acc[mi][ni][1] * ws1;
                s1 += acc[mi][ni][2] * ws0 + acc[mi][ni][3] * ws1;
                d0 += acc[mi][ni][0] * wd0 + acc[mi][ni][1] * wd1;
                d1 += acc[mi][ni][2] * wd0 + acc[mi][ni][3] * wd1;
            }
            #pragma unroll
            for (int o = 1; o <= 2; o <<= 1) {
                s0 += __shfl_xor_sync(0xffffffffu, s0, o);
                s1 += __shfl_xor_sync(0xffffffffu, s1, o);
                d0 += __shfl_xor_sync(0xffffffffu, d0, o);
                d1 += __shfl_xor_sync(0xffffffffu, d1, o);
            }
            if (lr == 0) {
                int rl0 = wm * 32 + mi * 16 + lq;
                sred[rl0 * 2 + wn] = s0;
                sred[(rl0 + 8) * 2 + wn] = s1;
                sred[256 + rl0 * 2 + wn] = d0;
                sred[256 + (rl0 + 8) * 2 + wn] = d1;
            }
        }
        __syncthreads();
        if (tid < 128) {
            int gr = row0 + tid;
            if (gr < M) {
                g_as[gr * 3 + head] = sred[tid * 2] + sred[tid * 2 + 1];
                g_ad[gr * 3 + head] = sred[256 + tid * 2] + sred[256 + tid * 2 + 1];
            }
        }
    }
}

// ---------------- GAT aggregation: single pass, shfl-broadcast edge weights ----------------
// Chunk of 32 edges: each lane computes its edge's 3 exps (exp-once), then the
// gather loop broadcasts (src, w0..w2) from the owning lane. Unnormalized sum,
// scaled by 1/denom at the end (softmax scale-invariance).
__global__ void agg_kernel(const __half* __restrict__ h, const float* __restrict__ bias,
                           __half* __restrict__ o16) {
    int gw = (blockIdx.x * blockDim.x + threadIdx.x) >> 5;
    int lane = threadIdx.x & 31;
    if (gw >= NN) return;
    int beg = g_rowptr[gw], end = g_rowptr[gw + 1];
    float ad0 = g_ad[gw * 3 + 0], ad1 = g_ad[gw * 3 + 1], ad2 = g_ad[gw * 3 + 2];

    float d0 = 0.f, d1 = 0.f, d2 = 0.f;
    float2 a0 = make_float2(0.f, 0.f), a1 = a0, a2 = a0;

    for (int base = beg; base < end; base += 32) {
        int n = end - base; if (n > 32) n = 32;
        int s = 0; float e0 = 0.f, e1 = 0.f, e2 = 0.f;
        if (lane < n) {
            s = g_srcs[base + lane];
            e0 = __expf(lrelu(g_as[s * 3 + 0] + ad0));
            e1 = __expf(lrelu(g_as[s * 3 + 1] + ad1));
            e2 = __expf(lrelu(g_as[s * 3 + 2] + ad2));
            d0 += e0; d1 += e1; d2 += e2;
        }
        for (int j = 0; j < n; j++) {
            int   sj = __shfl_sync(0xffffffffu, s,  j);
            float w0 = __shfl_sync(0xffffffffu, e0, j);
            float w1 = __shfl_sync(0xffffffffu, e1, j);
            float w2 = __shfl_sync(0xffffffffu, e2, j);
            const __half2* hs = (const __half2*)(h + (size_t)sj * HC);
            float2 f0 = __half22float2(hs[lane]);
            float2 f1 = __half22float2(hs[32 + lane]);
            float2 f2 = __half22float2(hs[64 + lane]);
            a0.x += f0.x * w0; a0.y += f0.y * w0;
            a1.x += f1.x * w1; a1.y += f1.y * w1;
            a2.x += f2.x * w2; a2.y += f2.y * w2;
        }
    }
    d0 = wsum(d0); d1 = wsum(d1); d2 = wsum(d2);
    float i0 = 1.f / (d0 + 1e-16f), i1 = 1.f / (d1 + 1e-16f), i2 = 1.f / (d2 + 1e-16f);
    a0.x *= i0; a0.y *= i0;
    a1.x *= i1; a1.y *= i1;
    a2.x *= i2; a2.y *= i2;

    float2 av[3] = {a0, a1, a2};
    #pragma unroll
    for (int q = 0; q < 3; q++) {
        int c = q * 64 + 2 * lane;
        float v0 = elu_f(av[q].x + bias[c]);
        float v1 = elu_f(av[q].y + bias[c + 1]);
        *(__half2*)(o16 + (size_t)gw * HC + c) = __floats2half2_rn(v0, v1);
    }
}

// ---------------- side-stream resources ----------------
static cudaStream_t g_s2;
static cudaEvent_t  g_evFork, g_evCSR, g_evJoin;
static struct SideInit {
    SideInit() {
        cudaStreamCreateWithFlags(&g_s2, cudaStreamNonBlocking);
        cudaEventCreateWithFlags(&g_evFork, cudaEventDisableTiming);
        cudaEventCreateWithFlags(&g_evCSR,  cudaEventDisableTiming);
        cudaEventCreateWithFlags(&g_evJoin, cudaEventDisableTiming);
    }
} g_sideInit;

// ---------------- launch ----------------
extern "C" void kernel_launch(void* const* d_in, const int* in_sizes, int n_in,
                              void* d_out, int out_size) {
    const float* x     = (const float*)d_in[0];
    const int*   ei    = (const int*)  d_in[1];
    const float* W1    = (const float*)d_in[2];
    const float* asrc1 = (const float*)d_in[3];
    const float* adst1 = (const float*)d_in[4];
    const float* b1    = (const float*)d_in[5];
    const float* W2    = (const float*)d_in[6];
    const float* asrc2 = (const float*)d_in[7];
    const float* adst2 = (const float*)d_in[8];
    const float* b2    = (const float*)d_in[9];
    const float* Wf1   = (const float*)d_in[10];
    const float* bf1   = (const float*)d_in[11];
    const float* Wf2   = (const float*)d_in[12];
    const float* bf2   = (const float*)d_in[13];
    float* out = (float*)d_out;

    float *bf;
    __half *h, *hx16, *x16, *w1thi, *w1tlo, *w2thi, *w2tlo, *wfthi, *wftlo;
    cudaGetSymbolAddress((void**)&h,     g_h);
    cudaGetSymbolAddress((void**)&hx16,  g_hx16);
    cudaGetSymbolAddress((void**)&x16,   g_x16);
    cudaGetSymbolAddress((void**)&bf,    g_bf);
    cudaGetSymbolAddress((void**)&w1thi, g_w1thi);
    cudaGetSymbolAddress((void**)&w1tlo, g_w1tlo);
    cudaGetSymbolAddress((void**)&w2thi, g_w2thi);
    cudaGetSymbolAddress((void**)&w2tlo, g_w2tlo);
    cudaGetSymbolAddress((void**)&wfthi, g_wfthi);
    cudaGetSymbolAddress((void**)&wftlo, g_wftlo);

    const int* srcp = ei;
    const int* dstp = ei + EE;

    cudaFuncSetAttribute(gemm_f16<true, true>,   cudaFuncAttributeMaxDynamicSharedMemorySize, SMEMB);
    cudaFuncSetAttribute(gemm_f16<false, false>, cudaFuncAttributeMaxDynamicSharedMemorySize, SMEMB);

    int warpBlocks = (NN * 32 + 255) / 256;
    int gy = (NN + BM - 1) / BM;

    // ---- fork: CSR build + W2/MLP weight prep on side stream ----
    cudaEventRecord(g_evFork, 0);
    cudaStreamWaitEvent(g_s2, g_evFork, 0);
    zero_kernel<<<(NN + 255) / 256, 256, 0, g_s2>>>();
    count_kernel<<<(ET + 255) / 256, 256, 0, g_s2>>>(dstp);
    scan_kernel<<<1, 1024, 0, g_s2>>>();
    bucket_kernel<<<(ET + 255) / 256, 256, 0, g_s2>>>(srcp, dstp);
    cudaEventRecord(g_evCSR, g_s2);                          // agg1 gate
    wsplit_kernel<<<(HC * HC + 255) / 256, 256, 0, g_s2>>>(W2, w2thi, w2tlo, HC, HC);
    fuse_mlp_kernel<<<(HC * OUTC + OUTC + 255) / 256, 256, 0, g_s2>>>(Wf1, bf1, Wf2, bf2);
    cudaEventRecord(g_evJoin, g_s2);                         // gemm2/gemm3 weights gate

    // ---- main stream: merged prep + layer-1 GEMM (+fused alpha) ----
    prep_kernel<<<(NN * INC / 4 + INC * HC + 255) / 256, 256>>>(x, x16, W1, w1thi, w1tlo);
    gemm_f16<true, true><<<dim3(HC / BN, gy), 256, SMEMB>>>(x16, w1thi, w1tlo, nullptr, h,
                                                            asrc1, adst1, NN, INC, HC);

    // ---- join 1: agg needs only the CSR ----
    cudaStreamWaitEvent(0, g_evCSR, 0);
    agg_kernel<<<warpBlocks, 256>>>(h, b1, hx16);

    // ---- join 2: gemm2 needs W2 tables (wsplit/fuse overlap agg1) ----
    cudaStreamWaitEvent(0, g_evJoin, 0);
    gemm_f16<true, true><<<dim3(HC / BN, gy), 256, SMEMB>>>(hx16, w2thi, w2tlo, nullptr, h,
                                                            asrc2, adst2, NN, HC, HC);
    agg_kernel<<<warpBlocks, 256>>>(h, b2, hx16);

    // fused MLP head
    gemm_f16<false, false><<<dim3(1, gy), 256, SMEMB>>>(hx16, wfthi, wftlo, bf, out,
                                                        nullptr, nullptr, NN, HC, OUTC);
}